// round 10
// baseline (speedup 1.0000x reference)
#include <cuda_runtime.h>
#include <math.h>

#define BB  16
#define CC  64
#define HH  128
#define WW  128
#define HW  (HH*WW)
#define BC  (BB*CC)

// Per-(b,c) x-space threshold T = logit(sigmoid(max x) - 0.01).
__device__ float g_T[BC];
// Order-preserving encoded per-plane max (atomicMax target). memset to 0 each launch.
__device__ unsigned g_enc[BC];

__device__ __forceinline__ float sigmoidf_(float v) {
    return 1.0f / (1.0f + expf(-v));
}
__device__ __forceinline__ unsigned enc_f(float f) {
    unsigned u = __float_as_uint(f);
    return (u & 0x80000000u) ? ~u : (u | 0x80000000u);
}
__device__ __forceinline__ float dec_f(unsigned k) {
    unsigned u = (k & 0x80000000u) ? (k & 0x7FFFFFFFu) : ~k;
    return __uint_as_float(u);
}

// ---------------------------------------------------------------------------
// K1a: plane max, 4 segment-blocks per plane, atomicMax on encoded key.
// grid = BC*4, 256 threads, 4 float4 per thread (4096 floats per block).
// ---------------------------------------------------------------------------
__global__ __launch_bounds__(256) void k1a_max(const float* __restrict__ x)
{
    const int bc  = blockIdx.x >> 2;
    const int seg = blockIdx.x & 3;
    const int t   = threadIdx.x;
    const float4* xp = (const float4*)(x + (size_t)bc * HW) + seg * 1024;

    float mx = -INFINITY;
    #pragma unroll
    for (int j = 0; j < 4; ++j) {
        float4 v = __ldg(xp + j * 256 + t);
        mx = fmaxf(fmaxf(fmaxf(mx, v.x), fmaxf(v.y, v.z)), v.w);
    }
    #pragma unroll
    for (int o = 16; o; o >>= 1) mx = fmaxf(mx, __shfl_xor_sync(0xffffffffu, mx, o));
    __shared__ float red[8];
    if ((t & 31) == 0) red[t >> 5] = mx;
    __syncthreads();
    if (t == 0) {
        float v = red[0];
        #pragma unroll
        for (int k = 1; k < 8; ++k) v = fmaxf(v, red[k]);
        atomicMax(&g_enc[bc], enc_f(v));
    }
}

// ---------------------------------------------------------------------------
// K1b: decode max -> ps, T. Writes g_T and bbox cols 0,5.
// ---------------------------------------------------------------------------
__global__ __launch_bounds__(256) void k1b_thresh(float* __restrict__ out)
{
    const int bc = blockIdx.x * 256 + threadIdx.x;
    if (bc >= BC) return;
    float v  = dec_f(g_enc[bc]);
    float ps = sigmoidf_(v);
    float M  = ps - 0.01f;
    float T;
    if (M > 0.0f) {
        double dM = (double)M;
        T = (float)log(dM / (1.0 - dM));
    } else {
        T = -INFINITY;
    }
    g_T[bc] = T;
    float* bb = out + (size_t)BB * 3 * CC * HW + (size_t)bc * 6;
    bb[0] = (float)(bc / CC);
    bb[5] = ps;
}

// ---------------------------------------------------------------------------
// FAT kernel: blocks [0,256) = k2 fused conv/argmax (round-9 code);
//             blocks [256,1280) = k1c masked bbox sums (hidden under k2).
// ---------------------------------------------------------------------------
#define RG 8
#define TR 18
#define TP 144
#define NFILL 9
#define TILE_SZ (TR * TP)

__global__ __launch_bounds__(256) void k_fat(
    const float* __restrict__ x,
    const float* __restrict__ w_bbx,
    const float* __restrict__ w_width,
    const float* __restrict__ w_width_sh,
    const float* __restrict__ w_height,
    const float* __restrict__ w_height_sh,
    float* __restrict__ out)
{
    const int t = threadIdx.x;

    // ======================= k1c: masked sums / bbox =======================
    if (blockIdx.x >= 256) {
        const int bc = blockIdx.x - 256;
        const int c  = bc % CC;
        const float* __restrict__ xp = x + (size_t)bc * HW;
        const float T = g_T[bc];

        float cw[11], ch[11];
        #pragma unroll
        for (int k = 0; k < 11; ++k) { cw[k] = w_width[c*11+k]; ch[k] = w_height[c*11+k]; }
        const float s0 = w_bbx[c] * 128.0f;
        const float sW = s0 * w_width_sh[c];
        const float sH = s0 * w_height_sh[c];

        float S = 0.f, Sc = 0.f, Sr = 0.f, Sw = 0.f, Sh = 0.f;
        #pragma unroll
        for (int j = 0; j < 16; ++j) {
            const int i0 = 1024 * j + 4 * t;
            float4 v4 = *(const float4*)(xp + i0);
            float vv[4] = {v4.x, v4.y, v4.z, v4.w};
            if (vv[0] > T || vv[1] > T || vv[2] > T || vv[3] > T) {
                #pragma unroll
                for (int u = 0; u < 4; ++u) {
                    float v = vv[u];
                    if (v > T) {
                        int i = i0 + u;
                        int row = i >> 7, col = i & 127;
                        S  += v;
                        Sc += (float)col * v;
                        Sr += (float)row * v;
                        float wvv = 0.f;
                        #pragma unroll
                        for (int k = 0; k < 11; ++k) {
                            int cc2 = col - 5 + k;
                            if (cc2 >= 0 && cc2 < WW) wvv = fmaf(xp[(row << 7) + cc2], cw[k], wvv);
                        }
                        float hvv = 0.f;
                        #pragma unroll
                        for (int k = 0; k < 11; ++k) {
                            int rr = row - 5 + k;
                            if (rr >= 0 && rr < HH) hvv = fmaf(xp[(rr << 7) + col], ch[k], hvv);
                        }
                        Sw += wvv * sW * v;
                        Sh += hvv * sH * v;
                    }
                }
            }
        }
        __shared__ float racc[5][8];
        #pragma unroll
        for (int o = 16; o; o >>= 1) {
            S  += __shfl_xor_sync(0xffffffffu, S,  o);
            Sc += __shfl_xor_sync(0xffffffffu, Sc, o);
            Sr += __shfl_xor_sync(0xffffffffu, Sr, o);
            Sw += __shfl_xor_sync(0xffffffffu, Sw, o);
            Sh += __shfl_xor_sync(0xffffffffu, Sh, o);
        }
        if ((t & 31) == 0) {
            int w5 = t >> 5;
            racc[0][w5] = S; racc[1][w5] = Sc; racc[2][w5] = Sr; racc[3][w5] = Sw; racc[4][w5] = Sh;
        }
        __syncthreads();
        if (t == 0) {
            float a0=0,a1=0,a2=0,a3=0,a4=0;
            #pragma unroll
            for (int k = 0; k < 8; ++k) { a0+=racc[0][k]; a1+=racc[1][k]; a2+=racc[2][k]; a3+=racc[3][k]; a4+=racc[4][k]; }
            float ws = a3 / a0, hs = a4 / a0;
            float x1 = a1 / a0 - ws * 0.5f;
            float y1 = a2 / a0 - hs * 0.5f;
            float* bb = out + (size_t)BB * 3 * CC * HW + (size_t)bc * 6;
            bb[1] = x1; bb[2] = y1;
            bb[3] = x1 + ws;  bb[4] = y1 + hs;
        }
        return;
    }

    // ======================= k2: fused conv/argmax =========================
    __shared__ float tile[4][TILE_SZ];   // ring of 4 (2 pairs)
    __shared__ float scw[CC * 11], sch[CC * 11];
    __shared__ float ssW[CC], ssH[CC], sTv[CC];

    const int b    = blockIdx.x >> 4;
    const int rg   = blockIdx.x & 15;
    const int row0 = rg * RG;
    const int r    = t >> 5;              // 0..7
    const int c4   = (t & 31) << 2;       // 0..124
    const int grow = row0 + r;

    for (int i = t; i < TILE_SZ; i += 256) {
        int col = i % TP;
        if (col < 8 || col >= 136) {
            tile[0][i] = 0.f; tile[1][i] = 0.f; tile[2][i] = 0.f; tile[3][i] = 0.f;
        }
    }
    for (int i = t; i < CC * 11; i += 256) { scw[i] = w_width[i]; sch[i] = w_height[i]; }
    if (t < CC) {
        float s0 = w_bbx[t] * 128.0f;
        ssW[t] = s0 * w_width_sh[t];
        ssH[t] = s0 * w_height_sh[t];
        sTv[t] = g_T[b * CC + t];
    }

    int   fidx[NFILL];
    bool  fok[NFILL];
    int   goff[NFILL];
    #pragma unroll
    for (int j = 0; j < NFILL; ++j) {
        int idx = t + j * 256;
        fidx[j] = (idx >> 7) * TP + 8 + (idx & 127);
        int gr  = row0 - 5 + (idx >> 7);
        fok[j]  = (gr >= 0 && gr < HH);
        goff[j] = (gr << 7) + (idx & 127);
    }

    float regs[2][NFILL];
    const float* xp0 = x + (size_t)(b * CC) * HW;

    #pragma unroll
    for (int p = 0; p < 2; ++p) {
        const float* xp = xp0 + (size_t)p * HW;
        #pragma unroll
        for (int j = 0; j < NFILL; ++j)
            regs[p][j] = fok[j] ? __ldg(xp + goff[j]) : 0.f;
        #pragma unroll
        for (int j = 0; j < NFILL; ++j)
            tile[p][fidx[j]] = regs[p][j];
    }

    float mS[4], mW[4], mH[4];
    int   iS[4], iW[4], iH[4];
    #pragma unroll
    for (int j = 0; j < 4; ++j) {
        mS[j] = -INFINITY; mW[j] = -INFINITY; mH[j] = -INFINITY;
        iS[j] = 0; iW[j] = 0; iH[j] = 0;
    }

    for (int cp = 0; cp < CC / 2; ++cp) {
        const int cur = (cp & 1) << 1;
        const int c0 = 2 * cp, c1 = 2 * cp + 1;

        if (cp + 1 < CC / 2) {
            #pragma unroll
            for (int p = 0; p < 2; ++p) {
                const float* xp = xp0 + (size_t)(2 * cp + 2 + p) * HW;
                #pragma unroll
                for (int j = 0; j < NFILL; ++j)
                    regs[p][j] = fok[j] ? __ldg(xp + goff[j]) : 0.f;
            }
        }
        __syncthreads();

        const float* tl0 = tile[cur];
        const float* tl1 = tile[cur + 1];

        float in0[20], in1[20];
        {
            const float* h0 = &tl0[(r + 5) * TP + c4];
            const float* h1 = &tl1[(r + 5) * TP + c4];
            #pragma unroll
            for (int m = 0; m < 5; ++m) {
                float4 v0 = *(const float4*)(h0 + 4 * m);
                float4 v1 = *(const float4*)(h1 + 4 * m);
                in0[4*m+0] = v0.x; in0[4*m+1] = v0.y; in0[4*m+2] = v0.z; in0[4*m+3] = v0.w;
                in1[4*m+0] = v1.x; in1[4*m+1] = v1.y; in1[4*m+2] = v1.z; in1[4*m+3] = v1.w;
            }
        }
        float hv0[4] = {0.f,0.f,0.f,0.f}, hv1[4] = {0.f,0.f,0.f,0.f};
        #pragma unroll
        for (int k = 0; k < 11; ++k) {
            float4 v0 = *(const float4*)(&tl0[(r + k) * TP + 8 + c4]);
            float4 v1 = *(const float4*)(&tl1[(r + k) * TP + 8 + c4]);
            float ck0 = sch[c0 * 11 + k];
            float ck1 = sch[c1 * 11 + k];
            hv0[0] = fmaf(v0.x, ck0, hv0[0]);  hv1[0] = fmaf(v1.x, ck1, hv1[0]);
            hv0[1] = fmaf(v0.y, ck0, hv0[1]);  hv1[1] = fmaf(v1.y, ck1, hv1[1]);
            hv0[2] = fmaf(v0.z, ck0, hv0[2]);  hv1[2] = fmaf(v1.z, ck1, hv1[2]);
            hv0[3] = fmaf(v0.w, ck0, hv0[3]);  hv1[3] = fmaf(v1.w, ck1, hv1[3]);
        }
        float wv0[4] = {0.f,0.f,0.f,0.f}, wv1[4] = {0.f,0.f,0.f,0.f};
        #pragma unroll
        for (int k = 0; k < 11; ++k) {
            float ck0 = scw[c0 * 11 + k];
            float ck1 = scw[c1 * 11 + k];
            wv0[0] = fmaf(in0[3 + k], ck0, wv0[0]);  wv1[0] = fmaf(in1[3 + k], ck1, wv1[0]);
            wv0[1] = fmaf(in0[4 + k], ck0, wv0[1]);  wv1[1] = fmaf(in1[4 + k], ck1, wv1[1]);
            wv0[2] = fmaf(in0[5 + k], ck0, wv0[2]);  wv1[2] = fmaf(in1[5 + k], ck1, wv1[2]);
            wv0[3] = fmaf(in0[6 + k], ck0, wv0[3]);  wv1[3] = fmaf(in1[6 + k], ck1, wv1[3]);
        }
        {
            const float sW0 = ssW[c0], sH0 = ssH[c0], T0 = sTv[c0];
            const float sW1 = ssW[c1], sH1 = ssH[c1], T1 = sTv[c1];
            #pragma unroll
            for (int j = 0; j < 4; ++j) {
                float w0 = wv0[j] * sW0, w1 = wv1[j] * sW1;
                float h0 = hv0[j] * sH0, h1 = hv1[j] * sH1;
                float x0 = in0[8 + j],   x1 = in1[8 + j];
                float s0 = (x0 > T0) ? x0 : 0.f;
                float s1 = (x1 > T1) ? x1 : 0.f;
                if (s0 > mS[j]) { mS[j] = s0; iS[j] = c0; }
                if (w0 > mW[j]) { mW[j] = w0; iW[j] = c0; }
                if (h0 > mH[j]) { mH[j] = h0; iH[j] = c0; }
                if (s1 > mS[j]) { mS[j] = s1; iS[j] = c1; }
                if (w1 > mW[j]) { mW[j] = w1; iW[j] = c1; }
                if (h1 > mH[j]) { mH[j] = h1; iH[j] = c1; }
            }
        }

        if (cp + 1 < CC / 2) {
            const int nxt = ((cp + 1) & 1) << 1;
            #pragma unroll
            for (int p = 0; p < 2; ++p) {
                float* tn = tile[nxt + p];
                #pragma unroll
                for (int j = 0; j < NFILL; ++j)
                    tn[fidx[j]] = regs[p][j];
            }
        }
    }

    // epilogue: zero-blast then scatter
    const size_t ob = (size_t)(b * 3 * CC) * HW + ((size_t)grow << 7) + c4;
    float* oS = out + ob;
    float* oW = oS + (size_t)CC * HW;
    float* oH = oS + (size_t)2 * CC * HW;
    const float4 z4 = make_float4(0.f, 0.f, 0.f, 0.f);
    #pragma unroll 4
    for (int c = 0; c < CC; ++c) {
        const size_t off = (size_t)c * HW;
        __stcs((float4*)(oS + off), z4);
        __stcs((float4*)(oW + off), z4);
        __stcs((float4*)(oH + off), z4);
    }
    #pragma unroll
    for (int j = 0; j < 4; ++j) {
        oS[(size_t)iS[j] * HW + j] = mS[j];
        oW[(size_t)iW[j] * HW + j] = mW[j];
        oH[(size_t)iH[j] * HW + j] = mH[j];
    }
}

extern "C" void kernel_launch(void* const* d_in, const int* in_sizes, int n_in,
                              void* d_out, int out_size)
{
    const float* x           = (const float*)d_in[0];
    const float* w_bbx       = (const float*)d_in[1];
    const float* w_width     = (const float*)d_in[2];
    const float* w_width_sh  = (const float*)d_in[3];
    const float* w_height    = (const float*)d_in[4];
    const float* w_height_sh = (const float*)d_in[5];
    float* out = (float*)d_out;

    // reset encoded-max buffer (captured memset node; 0 < enc(any float))
    void* enc_addr = nullptr;
    cudaGetSymbolAddress(&enc_addr, g_enc);
    cudaMemsetAsync(enc_addr, 0, BC * sizeof(unsigned));

    k1a_max<<<BC * 4, 256>>>(x);
    k1b_thresh<<<(BC + 255) / 256, 256>>>(out);
    k_fat<<<256 + BC, 256>>>(x, w_bbx, w_width, w_width_sh, w_height, w_height_sh, out);
}